// round 10
// baseline (speedup 1.0000x reference)
#include <cuda_runtime.h>

// OU Euler-Maruyama: x_{t+1} = a*x_t + b_t,  a = 1 - gamma*dt (const per chain).
// One warp per (n,m) chain (2048 warps), 64-thread CTAs.
// R9: 256-step tiles — lane L owns 8 consecutive steps (two float4 at
// stride-32B: idx 2L, 2L+1 within the tile's 64-float4 span). Same 5 shuffle
// scan rounds now move 2KB instead of 1KB: SHFL+issue count per byte halved
// (the only lever that has moved DRAM% so far is cutting per-byte serial
// work; warps/MLP/balance are all falsified). Scan weights a^8..a^128,
// carry advance a^256. 2-tile ILP groups. PF=6 ring (6KB/warp in flight).
// Tail: one dense 128-step tile covers float4s 4992..4999 (prefetched at
// kernel start so its latency is hidden behind the whole mainloop).

#define T_STEPS 20000
#define NV4     5000            // float4s per chain
#define N_CHAIN 2048
#define PF      6               // prefetch depth in 256-step tiles
#define NTILE   78              // 78*64 = 4992 float4s in main tiles
#define NMACRO  13              // 13 * 6 = 78

__global__ __launch_bounds__(64)
void oup_kernel(const float* __restrict__ theta,
                const float* __restrict__ noise,
                float*       __restrict__ out)
{
    const int warp = (blockIdx.x * blockDim.x + threadIdx.x) >> 5;
    const int lane = threadIdx.x & 31;
    if (warp >= N_CHAIN) return;

    const int n = warp >> 6;
    const float gamma = theta[n * 4 + 0];
    const float mu    = theta[n * 4 + 1];
    const float sigma = theta[n * 4 + 2];
    float x           = theta[n * 4 + 3];

    const float a   = 1.0f - gamma * 0.01f;  // dt = 0.01
    const float c0  = gamma * mu * 0.01f;
    const float ssd = sigma * 0.1f;          // sqrt(dt)

    const float a2   = a * a;
    const float a4   = a2 * a2;
    const float a8   = a4 * a4;
    const float a16  = a8 * a8;
    const float a32  = a16 * a16;
    const float a64  = a32 * a32;
    const float a128 = a64 * a64;
    const float a256 = a128 * a128;

    // a^(8*lane): exclusive-prefix coefficient (256-step tiles)
    float alane8 = 1.0f;
    if (lane & 1)  alane8 *= a8;
    if (lane & 2)  alane8 *= a16;
    if (lane & 4)  alane8 *= a32;
    if (lane & 8)  alane8 *= a64;
    if (lane & 16) alane8 *= a128;
    // a^(4*lane): for the dense 128-step tail tile
    float alane4 = 1.0f;
    if (lane & 1)  alane4 *= a4;
    if (lane & 2)  alane4 *= a8;
    if (lane & 4)  alane4 *= a16;
    if (lane & 8)  alane4 *= a32;
    if (lane & 16) alane4 *= a64;

    const float4* __restrict__ np = (const float4*)(noise + (size_t)warp * T_STEPS);
    float4*       __restrict__ op = (float4*)(out + (size_t)warp * T_STEPS);

    // Prefetch tail tile now (latency hidden behind whole mainloop)
    const int tidx = NTILE * 64 + lane;      // 4992 + lane
    float4 vtail = make_float4(0.f, 0.f, 0.f, 0.f);
    if (tidx < NV4) vtail = __ldcs(np + tidx);

    // Prefetch ring: PF tiles x 2 float4 per lane (stride-32B pair)
    float4 r0[PF], r1[PF];
#pragma unroll
    for (int k = 0; k < PF; ++k) {
        r0[k] = __ldcs(np + k * 64 + 2 * lane);
        r1[k] = __ldcs(np + k * 64 + 2 * lane + 1);
    }

    // ---- pair of 256-step tiles, scans interleaved (ILP=2) ----
    auto group2 = [&](const float4* v0, const float4* v1, int tile0) {
        float b[2][8], B[2];
#pragma unroll
        for (int j = 0; j < 2; ++j) {
            b[j][0] = fmaf(ssd, v0[j].x, c0);
            b[j][1] = fmaf(ssd, v0[j].y, c0);
            b[j][2] = fmaf(ssd, v0[j].z, c0);
            b[j][3] = fmaf(ssd, v0[j].w, c0);
            b[j][4] = fmaf(ssd, v1[j].x, c0);
            b[j][5] = fmaf(ssd, v1[j].y, c0);
            b[j][6] = fmaf(ssd, v1[j].z, c0);
            b[j][7] = fmaf(ssd, v1[j].w, c0);
            float Ba = b[j][0];
            Ba = fmaf(a, Ba, b[j][1]);
            Ba = fmaf(a, Ba, b[j][2]);
            Ba = fmaf(a, Ba, b[j][3]);
            float Bb = b[j][4];
            Bb = fmaf(a, Bb, b[j][5]);
            Bb = fmaf(a, Bb, b[j][6]);
            Bb = fmaf(a, Bb, b[j][7]);
            B[j] = fmaf(a4, Ba, Bb);         // inclusive agg over 8 steps
        }
#pragma unroll
        for (int s = 0; s < 5; ++s) {
            const int   d = 1 << s;
            const float w = (s == 0) ? a8 : (s == 1) ? a16 : (s == 2) ? a32
                          : (s == 3) ? a64 : a128;
            float t0 = __shfl_up_sync(0xFFFFFFFFu, B[0], d);
            float t1 = __shfl_up_sync(0xFFFFFFFFu, B[1], d);
            if (lane >= d) {
                B[0] = fmaf(w, t0, B[0]);
                B[1] = fmaf(w, t1, B[1]);
            }
        }
        float Bexcl[2], Btop[2];
#pragma unroll
        for (int j = 0; j < 2; ++j) {
            Bexcl[j] = __shfl_up_sync(0xFFFFFFFFu, B[j], 1);
            if (lane == 0) Bexcl[j] = 0.0f;
            Btop[j] = __shfl_sync(0xFFFFFFFFu, B[j], 31);
        }
#pragma unroll
        for (int j = 0; j < 2; ++j) {
            const float xs = fmaf(alane8, x, Bexcl[j]);
            const float y0 = fmaf(a, xs, b[j][0]);
            const float y1 = fmaf(a, y0, b[j][1]);
            const float y2 = fmaf(a, y1, b[j][2]);
            const float y3 = fmaf(a, y2, b[j][3]);
            const float y4 = fmaf(a, y3, b[j][4]);
            const float y5 = fmaf(a, y4, b[j][5]);
            const float y6 = fmaf(a, y5, b[j][6]);
            const float y7 = fmaf(a, y6, b[j][7]);
            const int base = (tile0 + j) * 64 + 2 * lane;
            __stcs(op + base,     make_float4(y0, y1, y2, y3));
            __stcs(op + base + 1, make_float4(y4, y5, y6, y7));
            x = fmaf(a256, x, Btop[j]);      // advance 256 steps
        }
    };

    for (int mi = 0; mi < NMACRO; ++mi) {
#pragma unroll
        for (int h = 0; h < 3; ++h) {
            const int slot = 2 * h;              // ring slots {0,1},{2,3},{4,5}
            const int i0   = mi * PF + slot;
            float4 v0[2], v1[2];
#pragma unroll
            for (int j = 0; j < 2; ++j) { v0[j] = r0[slot + j]; v1[j] = r1[slot + j]; }
            // batched refill (guard only the final macro-iteration's overrun)
#pragma unroll
            for (int j = 0; j < 2; ++j) {
                const int rt = i0 + PF + j;
                if (rt < NTILE) {
                    r0[slot + j] = __ldcs(np + rt * 64 + 2 * lane);
                    r1[slot + j] = __ldcs(np + rt * 64 + 2 * lane + 1);
                }
            }
            group2(v0, v1, i0);
        }
    }

    // Dense 128-step tail tile: float4s 4992..4999 (lanes 0..7 active)
    {
        const float b0 = fmaf(ssd, vtail.x, c0);
        const float b1 = fmaf(ssd, vtail.y, c0);
        const float b2 = fmaf(ssd, vtail.z, c0);
        const float b3 = fmaf(ssd, vtail.w, c0);
        float B = b0;
        B = fmaf(a, B, b1);
        B = fmaf(a, B, b2);
        B = fmaf(a, B, b3);
        float t;
        t = __shfl_up_sync(0xFFFFFFFFu, B, 1);  if (lane >= 1)  B = fmaf(a4,  t, B);
        t = __shfl_up_sync(0xFFFFFFFFu, B, 2);  if (lane >= 2)  B = fmaf(a8,  t, B);
        t = __shfl_up_sync(0xFFFFFFFFu, B, 4);  if (lane >= 4)  B = fmaf(a16, t, B);
        t = __shfl_up_sync(0xFFFFFFFFu, B, 8);  if (lane >= 8)  B = fmaf(a32, t, B);
        t = __shfl_up_sync(0xFFFFFFFFu, B, 16); if (lane >= 16) B = fmaf(a64, t, B);
        float Bexcl = __shfl_up_sync(0xFFFFFFFFu, B, 1);
        if (lane == 0) Bexcl = 0.0f;
        const float xs = fmaf(alane4, x, Bexcl);
        const float y0 = fmaf(a, xs, b0);
        const float y1 = fmaf(a, y0, b1);
        const float y2 = fmaf(a, y1, b2);
        const float y3 = fmaf(a, y2, b3);
        if (tidx < NV4) __stcs(op + tidx, make_float4(y0, y1, y2, y3));
    }
}

extern "C" void kernel_launch(void* const* d_in, const int* in_sizes, int n_in,
                              void* d_out, int out_size)
{
    const float* theta = (const float*)d_in[0];   // [32,4]
    const float* noise = (const float*)d_in[1];   // [32,64,20000]
    float* out = (float*)d_out;                   // [32,64,20000]
    (void)in_sizes; (void)n_in; (void)out_size;
    oup_kernel<<<N_CHAIN / 2, 64>>>(theta, noise, out);
}

// round 11
// speedup vs baseline: 1.0991x; 1.0991x over previous
#include <cuda_runtime.h>

// OU Euler-Maruyama: x_{t+1} = a*x_t + b_t,  a = 1 - gamma*dt (const per chain).
// One warp per (n,m) chain (2048 warps), 64-thread CTAs.
// R10 = R7 compute structure (group-of-4 interleaved warp scans, ILP=4 on the
// 5 SHFL rounds; unit-stride float4 tiles -> each LDG.128 touches exactly 4
// 128B lines — R9 proved wider lane strides double L1tex wavefronts and
// regress) with ONE change: all 8 ring refills are front-batched per
// macro-iteration (one contiguous 4KB burst per warp) to improve DRAM row
// locality vs 2KB half-bursts. Streaming hints __ldcs/__stcs throughout.

#define T_STEPS 20000
#define NV4     5000            // T_STEPS/4 float4s per chain
#define N_CHAIN 2048            // 32 * 64
#define PF      8               // prefetch depth (tiles)
#define NMAIN   19              // 19*8 = 152 tiles in main loop

__device__ __forceinline__ float4 load_tile(const float4* __restrict__ np,
                                            int tile, int lane) {
    int idx = tile * 32 + lane;
    if (idx < NV4) return __ldcs(np + idx);
    return make_float4(0.f, 0.f, 0.f, 0.f);
}

__global__ __launch_bounds__(64)
void oup_kernel(const float* __restrict__ theta,
                const float* __restrict__ noise,
                float*       __restrict__ out)
{
    const int warp = (blockIdx.x * blockDim.x + threadIdx.x) >> 5;
    const int lane = threadIdx.x & 31;
    if (warp >= N_CHAIN) return;

    const int n = warp >> 6;                 // chain-param row
    const float gamma = theta[n * 4 + 0];
    const float mu    = theta[n * 4 + 1];
    const float sigma = theta[n * 4 + 2];
    float x           = theta[n * 4 + 3];    // running state (carry)

    const float a   = 1.0f - gamma * 0.01f;  // dt = 0.01
    const float c0  = gamma * mu * 0.01f;
    const float ssd = sigma * 0.1f;          // sqrt(dt) = 0.1

    const float a2   = a * a;
    const float a4   = a2 * a2;
    const float a8   = a4 * a4;
    const float a16  = a8 * a8;
    const float a32  = a16 * a16;
    const float a64  = a32 * a32;
    const float a128 = a64 * a64;

    // a^(4*lane): exclusive-prefix coefficient for this lane's start state
    float alane = 1.0f;
    if (lane & 1)  alane *= a4;
    if (lane & 2)  alane *= a8;
    if (lane & 4)  alane *= a16;
    if (lane & 8)  alane *= a32;
    if (lane & 16) alane *= a64;

    const float4* __restrict__ np = (const float4*)(noise + (size_t)warp * T_STEPS);
    float4*       __restrict__ op = (float4*)(out + (size_t)warp * T_STEPS);

    // Prefetch ring (tiles 0..7 in-bounds)
    float4 buf[PF];
#pragma unroll
    for (int k = 0; k < PF; ++k) buf[k] = __ldcs(np + k * 32 + lane);

    // ---- 4-tile group: interleaved B-scans (ILP=4), serial carry apply ----
    auto group4 = [&](const float4* v, int tile0) {
        float b[4][4], B[4];
#pragma unroll
        for (int j = 0; j < 4; ++j) {
            b[j][0] = fmaf(ssd, v[j].x, c0);
            b[j][1] = fmaf(ssd, v[j].y, c0);
            b[j][2] = fmaf(ssd, v[j].z, c0);
            b[j][3] = fmaf(ssd, v[j].w, c0);
            float t = b[j][0];
            t = fmaf(a, t, b[j][1]);
            t = fmaf(a, t, b[j][2]);
            B[j] = fmaf(a, t, b[j][3]);
        }
        // 5 scan rounds, 4 independent SHFL+FMA per round
#pragma unroll
        for (int s = 0; s < 5; ++s) {
            const int   d = 1 << s;
            const float w = (s == 0) ? a4 : (s == 1) ? a8 : (s == 2) ? a16
                          : (s == 3) ? a32 : a64;
            float t0 = __shfl_up_sync(0xFFFFFFFFu, B[0], d);
            float t1 = __shfl_up_sync(0xFFFFFFFFu, B[1], d);
            float t2 = __shfl_up_sync(0xFFFFFFFFu, B[2], d);
            float t3 = __shfl_up_sync(0xFFFFFFFFu, B[3], d);
            if (lane >= d) {
                B[0] = fmaf(w, t0, B[0]);
                B[1] = fmaf(w, t1, B[1]);
                B[2] = fmaf(w, t2, B[2]);
                B[3] = fmaf(w, t3, B[3]);
            }
        }
        float Bexcl[4], Btop[4];
#pragma unroll
        for (int j = 0; j < 4; ++j) {
            Bexcl[j] = __shfl_up_sync(0xFFFFFFFFu, B[j], 1);
            if (lane == 0) Bexcl[j] = 0.0f;
            Btop[j] = __shfl_sync(0xFFFFFFFFu, B[j], 31);
        }
        // Serial carry across the 4 tiles (1 FMA deep per tile); outputs ILP
#pragma unroll
        for (int j = 0; j < 4; ++j) {
            const float xs = fmaf(alane, x, Bexcl[j]);
            const float y0 = fmaf(a, xs, b[j][0]);
            const float y1 = fmaf(a, y0, b[j][1]);
            const float y2 = fmaf(a, y1, b[j][2]);
            const float y3 = fmaf(a, y2, b[j][3]);
            __stcs(op + (tile0 + j) * 32 + lane, make_float4(y0, y1, y2, y3));
            x = fmaf(a128, x, Btop[j]);
        }
    };

    // Main: 19 macro-iters; ALL 8 refills front-batched (4KB contiguous burst)
    for (int mi = 0; mi < NMAIN; ++mi) {
        const int i0 = mi * PF;
        float4 v[PF];
#pragma unroll
        for (int k = 0; k < PF; ++k) v[k] = buf[k];
#pragma unroll
        for (int k = 0; k < PF; ++k)
            buf[k] = load_tile(np, i0 + PF + k, lane);   // 8 back-to-back LDG.128
        group4(v,     i0);
        group4(v + 4, i0 + 4);
    }
    // Tiles 152..155 (in-bounds: 156*32 = 4992 <= 5000), from ring, no refill
    {
        float4 v[4];
#pragma unroll
        for (int j = 0; j < 4; ++j) v[j] = buf[j];
        group4(v, NMAIN * PF);
    }
    // Tail tile 156 (partial: lanes with idx < 5000)
    {
        const float4 v = buf[4];
        const float b0 = fmaf(ssd, v.x, c0);
        const float b1 = fmaf(ssd, v.y, c0);
        const float b2 = fmaf(ssd, v.z, c0);
        const float b3 = fmaf(ssd, v.w, c0);
        float B = b0;
        B = fmaf(a, B, b1);
        B = fmaf(a, B, b2);
        B = fmaf(a, B, b3);
        float t;
        t = __shfl_up_sync(0xFFFFFFFFu, B, 1);  if (lane >= 1)  B = fmaf(a4,  t, B);
        t = __shfl_up_sync(0xFFFFFFFFu, B, 2);  if (lane >= 2)  B = fmaf(a8,  t, B);
        t = __shfl_up_sync(0xFFFFFFFFu, B, 4);  if (lane >= 4)  B = fmaf(a16, t, B);
        t = __shfl_up_sync(0xFFFFFFFFu, B, 8);  if (lane >= 8)  B = fmaf(a32, t, B);
        t = __shfl_up_sync(0xFFFFFFFFu, B, 16); if (lane >= 16) B = fmaf(a64, t, B);
        float Bexcl = __shfl_up_sync(0xFFFFFFFFu, B, 1);
        if (lane == 0) Bexcl = 0.0f;
        const float xs = fmaf(alane, x, Bexcl);
        const float y0 = fmaf(a, xs, b0);
        const float y1 = fmaf(a, y0, b1);
        const float y2 = fmaf(a, y1, b2);
        const float y3 = fmaf(a, y2, b3);
        const int idx = (NMAIN * PF + 4) * 32 + lane;
        if (idx < NV4) __stcs(op + idx, make_float4(y0, y1, y2, y3));
    }
}

extern "C" void kernel_launch(void* const* d_in, const int* in_sizes, int n_in,
                              void* d_out, int out_size)
{
    const float* theta = (const float*)d_in[0];   // [32,4]
    const float* noise = (const float*)d_in[1];   // [32,64,20000]
    float* out = (float*)d_out;                   // [32,64,20000]
    (void)in_sizes; (void)n_in; (void)out_size;
    oup_kernel<<<N_CHAIN / 2, 64>>>(theta, noise, out);
}

// round 13
// speedup vs baseline: 1.1009x; 1.0017x over previous
#include <cuda_runtime.h>

// OU Euler-Maruyama: x_{t+1} = a*x_t + b_t,  a = 1 - gamma*dt (const per chain).
// One warp per (n,m) chain (2048 warps), 64-thread CTAs.
// Compute: group-of-4 interleaved constant-coefficient warp scans (R7),
// unit-stride float4 tiles, PF=8 LDG ring with front-batched 4KB refill (R10).
// R11: store stream decoupled — results go to smem via STS.128 and one
// elected lane issues a single 4KB cp.async.bulk (smem->global) per
// macro-iteration. Warp never blocks on DRAM writes (only wait_group.read of
// the PREVIOUS bulk, which had a full macro-iter to drain its smem reads);
// DRAM sees contiguous 4KB write bursts per stream. Tail (tiles 152..156,
// 2176B) also goes through one bulk store — zero STG in the kernel.

#define T_STEPS 20000
#define NV4     5000            // T_STEPS/4 float4s per chain
#define N_CHAIN 2048            // 32 * 64
#define PF      8               // prefetch depth (tiles)
#define NMAIN   19              // 19*8 = 152 tiles in main loop

__device__ __forceinline__ float4 load_tile(const float4* __restrict__ np,
                                            int tile, int lane) {
    int idx = tile * 32 + lane;
    if (idx < NV4) return __ldcs(np + idx);
    return make_float4(0.f, 0.f, 0.f, 0.f);
}

__device__ __forceinline__ unsigned smem_u32(const void* p) {
    unsigned a;
    asm("{ .reg .u64 t; cvta.to.shared.u64 t, %1; cvt.u32.u64 %0, t; }"
        : "=r"(a) : "l"(p));
    return a;
}

__global__ __launch_bounds__(64)
void oup_kernel(const float* __restrict__ theta,
                const float* __restrict__ noise,
                float*       __restrict__ out)
{
    __shared__ float4 stb[2][256];           // 4KB store buffer per warp

    const int warp = (blockIdx.x * blockDim.x + threadIdx.x) >> 5;
    const int wlo  = (threadIdx.x >> 5) & 1; // warp index within CTA
    const int lane = threadIdx.x & 31;
    if (warp >= N_CHAIN) return;

    const int n = warp >> 6;                 // chain-param row
    const float gamma = theta[n * 4 + 0];
    const float mu    = theta[n * 4 + 1];
    const float sigma = theta[n * 4 + 2];
    float x           = theta[n * 4 + 3];    // running state (carry)

    const float a   = 1.0f - gamma * 0.01f;  // dt = 0.01
    const float c0  = gamma * mu * 0.01f;
    const float ssd = sigma * 0.1f;          // sqrt(dt) = 0.1

    const float a2   = a * a;
    const float a4   = a2 * a2;
    const float a8   = a4 * a4;
    const float a16  = a8 * a8;
    const float a32  = a16 * a16;
    const float a64  = a32 * a32;
    const float a128 = a64 * a64;

    // a^(4*lane): exclusive-prefix coefficient for this lane's start state
    float alane = 1.0f;
    if (lane & 1)  alane *= a4;
    if (lane & 2)  alane *= a8;
    if (lane & 4)  alane *= a16;
    if (lane & 8)  alane *= a32;
    if (lane & 16) alane *= a64;

    const float4* __restrict__ np = (const float4*)(noise + (size_t)warp * T_STEPS);
    float4*       __restrict__ op = (float4*)(out + (size_t)warp * T_STEPS);

    float4* const     sb    = stb[wlo];
    const unsigned    sbu   = smem_u32(sb);
    const bool        lead  = (lane == 0);

    // Prefetch ring (tiles 0..7 in-bounds)
    float4 buf[PF];
#pragma unroll
    for (int k = 0; k < PF; ++k) buf[k] = __ldcs(np + k * 32 + lane);

    // ---- 4-tile group: interleaved B-scans (ILP=4); outputs -> smem slot ----
    auto group4 = [&](const float4* v, int slot0) {
        float b[4][4], B[4];
#pragma unroll
        for (int j = 0; j < 4; ++j) {
            b[j][0] = fmaf(ssd, v[j].x, c0);
            b[j][1] = fmaf(ssd, v[j].y, c0);
            b[j][2] = fmaf(ssd, v[j].z, c0);
            b[j][3] = fmaf(ssd, v[j].w, c0);
            float t = b[j][0];
            t = fmaf(a, t, b[j][1]);
            t = fmaf(a, t, b[j][2]);
            B[j] = fmaf(a, t, b[j][3]);
        }
#pragma unroll
        for (int s = 0; s < 5; ++s) {
            const int   d = 1 << s;
            const float w = (s == 0) ? a4 : (s == 1) ? a8 : (s == 2) ? a16
                          : (s == 3) ? a32 : a64;
            float t0 = __shfl_up_sync(0xFFFFFFFFu, B[0], d);
            float t1 = __shfl_up_sync(0xFFFFFFFFu, B[1], d);
            float t2 = __shfl_up_sync(0xFFFFFFFFu, B[2], d);
            float t3 = __shfl_up_sync(0xFFFFFFFFu, B[3], d);
            if (lane >= d) {
                B[0] = fmaf(w, t0, B[0]);
                B[1] = fmaf(w, t1, B[1]);
                B[2] = fmaf(w, t2, B[2]);
                B[3] = fmaf(w, t3, B[3]);
            }
        }
        float Bexcl[4], Btop[4];
#pragma unroll
        for (int j = 0; j < 4; ++j) {
            Bexcl[j] = __shfl_up_sync(0xFFFFFFFFu, B[j], 1);
            if (lane == 0) Bexcl[j] = 0.0f;
            Btop[j] = __shfl_sync(0xFFFFFFFFu, B[j], 31);
        }
#pragma unroll
        for (int j = 0; j < 4; ++j) {
            const float xs = fmaf(alane, x, Bexcl[j]);
            const float y0 = fmaf(a, xs, b[j][0]);
            const float y1 = fmaf(a, y0, b[j][1]);
            const float y2 = fmaf(a, y1, b[j][2]);
            const float y3 = fmaf(a, y2, b[j][3]);
            sb[(slot0 + j) * 32 + lane] = make_float4(y0, y1, y2, y3); // STS.128
            x = fmaf(a128, x, Btop[j]);
        }
    };

    // Main: 19 macro-iters of 8 tiles; one 4KB bulk store per iteration
    for (int mi = 0; mi < NMAIN; ++mi) {
        const int i0 = mi * PF;
        float4 v[PF];
#pragma unroll
        for (int k = 0; k < PF; ++k) v[k] = buf[k];
#pragma unroll
        for (int k = 0; k < PF; ++k)
            buf[k] = load_tile(np, i0 + PF + k, lane);   // 4KB refill burst

        // Previous bulk store must have finished READING the smem buffer
        if (lead) asm volatile("cp.async.bulk.wait_group.read 0;" ::: "memory");
        __syncwarp();

        group4(v,     0);
        group4(v + 4, 4);
        __syncwarp();

        if (lead) {
            asm volatile("fence.proxy.async.shared::cta;" ::: "memory");
            asm volatile(
                "cp.async.bulk.global.shared::cta.bulk_group [%0], [%1], %2;"
                :: "l"((void*)(op + i0 * 32)), "r"(sbu), "r"(4096) : "memory");
            asm volatile("cp.async.bulk.commit_group;" ::: "memory");
        }
    }

    // Tail: tiles 152..155 (full) + tile 156 (lanes 0..7) -> one 2176B bulk
    {
        if (lead) asm volatile("cp.async.bulk.wait_group.read 0;" ::: "memory");
        __syncwarp();

        float4 v[4];
#pragma unroll
        for (int j = 0; j < 4; ++j) v[j] = buf[j];
        group4(v, 0);                          // tiles 152..155 -> slots 0..3

        // tile 156 (partial): full-warp scan, lanes 0..7 store
        {
            const float4 vt = buf[4];
            const float b0 = fmaf(ssd, vt.x, c0);
            const float b1 = fmaf(ssd, vt.y, c0);
            const float b2 = fmaf(ssd, vt.z, c0);
            const float b3 = fmaf(ssd, vt.w, c0);
            float B = b0;
            B = fmaf(a, B, b1);
            B = fmaf(a, B, b2);
            B = fmaf(a, B, b3);
            float t;
            t = __shfl_up_sync(0xFFFFFFFFu, B, 1);  if (lane >= 1)  B = fmaf(a4,  t, B);
            t = __shfl_up_sync(0xFFFFFFFFu, B, 2);  if (lane >= 2)  B = fmaf(a8,  t, B);
            t = __shfl_up_sync(0xFFFFFFFFu, B, 4);  if (lane >= 4)  B = fmaf(a16, t, B);
            t = __shfl_up_sync(0xFFFFFFFFu, B, 8);  if (lane >= 8)  B = fmaf(a32, t, B);
            t = __shfl_up_sync(0xFFFFFFFFu, B, 16); if (lane >= 16) B = fmaf(a64, t, B);
            float Bexcl = __shfl_up_sync(0xFFFFFFFFu, B, 1);
            if (lane == 0) Bexcl = 0.0f;
            const float xs = fmaf(alane, x, Bexcl);
            const float y0 = fmaf(a, xs, b0);
            const float y1 = fmaf(a, y0, b1);
            const float y2 = fmaf(a, y1, b2);
            const float y3 = fmaf(a, y2, b3);
            if (lane < 8) sb[4 * 32 + lane] = make_float4(y0, y1, y2, y3);
        }
        __syncwarp();

        if (lead) {
            asm volatile("fence.proxy.async.shared::cta;" ::: "memory");
            asm volatile(
                "cp.async.bulk.global.shared::cta.bulk_group [%0], [%1], %2;"
                :: "l"((void*)(op + NMAIN * PF * 32)), "r"(sbu), "r"(2176) : "memory");
            asm volatile("cp.async.bulk.commit_group;" ::: "memory");
            // Ensure all bulk stores fully complete before thread exit
            asm volatile("cp.async.bulk.wait_group 0;" ::: "memory");
        }
        __syncwarp();
    }
}

extern "C" void kernel_launch(void* const* d_in, const int* in_sizes, int n_in,
                              void* d_out, int out_size)
{
    const float* theta = (const float*)d_in[0];   // [32,4]
    const float* noise = (const float*)d_in[1];   // [32,64,20000]
    float* out = (float*)d_out;                   // [32,64,20000]
    (void)in_sizes; (void)n_in; (void)out_size;
    oup_kernel<<<N_CHAIN / 2, 64>>>(theta, noise, out);
}

// round 15
// speedup vs baseline: 1.1064x; 1.0050x over previous
#include <cuda_runtime.h>

// OU Euler-Maruyama: x_{t+1} = a*x_t + b_t,  a = 1 - gamma*dt (const per chain).
// One warp per (n,m) chain (2048 warps), 64-thread CTAs.
// Structure = R10 best (group-of-4 interleaved warp scans, ILP=4 SHFL rounds;
// unit-stride float4 tiles so each LDG.128 touches exactly 4 lines; PF=8 ring
// with all 8 refills front-batched into one 4KB burst per macro-iteration).
// R13 single change: output stores use DEFAULT cache policy (was __stcs).
// Traffic audit: 48us x 5.72TB/s = 274MB HBM vs 328MB logical — L2 already
// retains ~54MB of dirty output EVEN marked evict-first. Evict-normal writes
// + evict-first (__ldcs) reads should retain ~100MB+ of the 164MB output in
// the 126MB L2, converting retained MB directly into saved HBM writes.

#define T_STEPS 20000
#define NV4     5000            // T_STEPS/4 float4s per chain
#define N_CHAIN 2048            // 32 * 64
#define PF      8               // prefetch depth (tiles)
#define NMAIN   19              // 19*8 = 152 tiles in main loop

__device__ __forceinline__ float4 load_tile(const float4* __restrict__ np,
                                            int tile, int lane) {
    int idx = tile * 32 + lane;
    if (idx < NV4) return __ldcs(np + idx);
    return make_float4(0.f, 0.f, 0.f, 0.f);
}

__global__ __launch_bounds__(64)
void oup_kernel(const float* __restrict__ theta,
                const float* __restrict__ noise,
                float*       __restrict__ out)
{
    const int warp = (blockIdx.x * blockDim.x + threadIdx.x) >> 5;
    const int lane = threadIdx.x & 31;
    if (warp >= N_CHAIN) return;

    const int n = warp >> 6;                 // chain-param row
    const float gamma = theta[n * 4 + 0];
    const float mu    = theta[n * 4 + 1];
    const float sigma = theta[n * 4 + 2];
    float x           = theta[n * 4 + 3];    // running state (carry)

    const float a   = 1.0f - gamma * 0.01f;  // dt = 0.01
    const float c0  = gamma * mu * 0.01f;
    const float ssd = sigma * 0.1f;          // sqrt(dt) = 0.1

    const float a2   = a * a;
    const float a4   = a2 * a2;
    const float a8   = a4 * a4;
    const float a16  = a8 * a8;
    const float a32  = a16 * a16;
    const float a64  = a32 * a32;
    const float a128 = a64 * a64;

    // a^(4*lane): exclusive-prefix coefficient for this lane's start state
    float alane = 1.0f;
    if (lane & 1)  alane *= a4;
    if (lane & 2)  alane *= a8;
    if (lane & 4)  alane *= a16;
    if (lane & 8)  alane *= a32;
    if (lane & 16) alane *= a64;

    const float4* __restrict__ np = (const float4*)(noise + (size_t)warp * T_STEPS);
    float4*       __restrict__ op = (float4*)(out + (size_t)warp * T_STEPS);

    // Prefetch ring (tiles 0..7 in-bounds)
    float4 buf[PF];
#pragma unroll
    for (int k = 0; k < PF; ++k) buf[k] = __ldcs(np + k * 32 + lane);

    // ---- 4-tile group: interleaved B-scans (ILP=4), serial carry apply ----
    auto group4 = [&](const float4* v, int tile0) {
        float b[4][4], B[4];
#pragma unroll
        for (int j = 0; j < 4; ++j) {
            b[j][0] = fmaf(ssd, v[j].x, c0);
            b[j][1] = fmaf(ssd, v[j].y, c0);
            b[j][2] = fmaf(ssd, v[j].z, c0);
            b[j][3] = fmaf(ssd, v[j].w, c0);
            float t = b[j][0];
            t = fmaf(a, t, b[j][1]);
            t = fmaf(a, t, b[j][2]);
            B[j] = fmaf(a, t, b[j][3]);
        }
        // 5 scan rounds, 4 independent SHFL+FMA per round
#pragma unroll
        for (int s = 0; s < 5; ++s) {
            const int   d = 1 << s;
            const float w = (s == 0) ? a4 : (s == 1) ? a8 : (s == 2) ? a16
                          : (s == 3) ? a32 : a64;
            float t0 = __shfl_up_sync(0xFFFFFFFFu, B[0], d);
            float t1 = __shfl_up_sync(0xFFFFFFFFu, B[1], d);
            float t2 = __shfl_up_sync(0xFFFFFFFFu, B[2], d);
            float t3 = __shfl_up_sync(0xFFFFFFFFu, B[3], d);
            if (lane >= d) {
                B[0] = fmaf(w, t0, B[0]);
                B[1] = fmaf(w, t1, B[1]);
                B[2] = fmaf(w, t2, B[2]);
                B[3] = fmaf(w, t3, B[3]);
            }
        }
        float Bexcl[4], Btop[4];
#pragma unroll
        for (int j = 0; j < 4; ++j) {
            Bexcl[j] = __shfl_up_sync(0xFFFFFFFFu, B[j], 1);
            if (lane == 0) Bexcl[j] = 0.0f;
            Btop[j] = __shfl_sync(0xFFFFFFFFu, B[j], 31);
        }
        // Serial carry across the 4 tiles (1 FMA deep per tile); outputs ILP
#pragma unroll
        for (int j = 0; j < 4; ++j) {
            const float xs = fmaf(alane, x, Bexcl[j]);
            const float y0 = fmaf(a, xs, b[j][0]);
            const float y1 = fmaf(a, y0, b[j][1]);
            const float y2 = fmaf(a, y1, b[j][2]);
            const float y3 = fmaf(a, y2, b[j][3]);
            op[(tile0 + j) * 32 + lane] = make_float4(y0, y1, y2, y3); // evict-normal
            x = fmaf(a128, x, Btop[j]);
        }
    };

    // Main: 19 macro-iters; ALL 8 refills front-batched (4KB contiguous burst)
    for (int mi = 0; mi < NMAIN; ++mi) {
        const int i0 = mi * PF;
        float4 v[PF];
#pragma unroll
        for (int k = 0; k < PF; ++k) v[k] = buf[k];
#pragma unroll
        for (int k = 0; k < PF; ++k)
            buf[k] = load_tile(np, i0 + PF + k, lane);   // 8 back-to-back LDG.128
        group4(v,     i0);
        group4(v + 4, i0 + 4);
    }
    // Tiles 152..155 (in-bounds: 156*32 = 4992 <= 5000), from ring, no refill
    {
        float4 v[4];
#pragma unroll
        for (int j = 0; j < 4; ++j) v[j] = buf[j];
        group4(v, NMAIN * PF);
    }
    // Tail tile 156 (partial: lanes with idx < 5000)
    {
        const float4 v = buf[4];
        const float b0 = fmaf(ssd, v.x, c0);
        const float b1 = fmaf(ssd, v.y, c0);
        const float b2 = fmaf(ssd, v.z, c0);
        const float b3 = fmaf(ssd, v.w, c0);
        float B = b0;
        B = fmaf(a, B, b1);
        B = fmaf(a, B, b2);
        B = fmaf(a, B, b3);
        float t;
        t = __shfl_up_sync(0xFFFFFFFFu, B, 1);  if (lane >= 1)  B = fmaf(a4,  t, B);
        t = __shfl_up_sync(0xFFFFFFFFu, B, 2);  if (lane >= 2)  B = fmaf(a8,  t, B);
        t = __shfl_up_sync(0xFFFFFFFFu, B, 4);  if (lane >= 4)  B = fmaf(a16, t, B);
        t = __shfl_up_sync(0xFFFFFFFFu, B, 8);  if (lane >= 8)  B = fmaf(a32, t, B);
        t = __shfl_up_sync(0xFFFFFFFFu, B, 16); if (lane >= 16) B = fmaf(a64, t, B);
        float Bexcl = __shfl_up_sync(0xFFFFFFFFu, B, 1);
        if (lane == 0) Bexcl = 0.0f;
        const float xs = fmaf(alane, x, Bexcl);
        const float y0 = fmaf(a, xs, b0);
        const float y1 = fmaf(a, y0, b1);
        const float y2 = fmaf(a, y1, b2);
        const float y3 = fmaf(a, y2, b3);
        const int idx = (NMAIN * PF + 4) * 32 + lane;
        if (idx < NV4) op[idx] = make_float4(y0, y1, y2, y3);
    }
}

extern "C" void kernel_launch(void* const* d_in, const int* in_sizes, int n_in,
                              void* d_out, int out_size)
{
    const float* theta = (const float*)d_in[0];   // [32,4]
    const float* noise = (const float*)d_in[1];   // [32,64,20000]
    float* out = (float*)d_out;                   // [32,64,20000]
    (void)in_sizes; (void)n_in; (void)out_size;
    oup_kernel<<<N_CHAIN / 2, 64>>>(theta, noise, out);
}